// round 13
// baseline (speedup 1.0000x reference)
#include <cuda_runtime.h>

#define BATCH   32
#define TSTEPS  1024
#define COLS    2048
#define THREADS 512            /* one CTA covers the whole row */
#define V       4              /* columns per thread (float4) */
#define WARPS   (THREADS / 32) /* 16 */
#define ROW4    (COLS / 4)     /* row stride in float4 = 512 */
#define DPF     8              /* x prefetch depth (time steps) */

__device__ __forceinline__ float smix(float a, float b) {
    float d = a - b;                       /* a - b          */
    float e = __expf(-d);                  /* MUFU.EX2 path  */
    float p = __fdividef(1.0f, 1.0f + e);  /* MUFU.RCP path  */
    return fmaf(p, d, b);                  /* b + p*(a-b)    */
}

__global__ __launch_bounds__(THREADS, 1)
void softscan_kernel(const float* __restrict__ x, float* __restrict__ out) {
    const int b    = blockIdx.x;          /* one CTA per batch row */
    const int tid  = threadIdx.x;
    const int lane = tid & 31;
    const int warp = tid >> 5;
    const int col0 = tid * V;

    __shared__ float sh[2][WARPS];        /* double-buffered warp-seam values */

    const float4* xp = (const float4*)(x   + (size_t)b * TSTEPS * COLS + col0);
    float4*       op = (float4*)      (out + (size_t)b * TSTEPS * COLS + col0);

    const bool seamer   = (lane == 31) && (warp != WARPS - 1);
    const bool firstcol = (tid == 0);     /* owns global column 0 */

    /* ---- t = 0: carry = x[b,0,:] ---- */
    float4 c = __ldcs(xp);
    __stcs(op, c);
    if (seamer) sh[0][warp] = c.w;

    /* x prefetch ring: buf[k] holds row t where (t-1)&7 == k */
    float4 buf[DPF];
    #pragma unroll
    for (int k = 0; k < DPF; ++k)
        buf[k] = __ldcs(xp + (size_t)(k + 1) * ROW4);
    __syncthreads();

    for (int tb = 1; tb < TSTEPS; tb += DPF) {
        #pragma unroll
        for (int k = 0; k < DPF; ++k) {
            const int t = tb + k;          /* (t-1)&7 == k by construction */
            if (t >= TSTEPS) break;

            float4 xv = buf[k];
            if (t + DPF < TSTEPS)
                buf[k] = __ldcs(xp + (size_t)(t + DPF) * ROW4);

            /* left neighbor's carry (col0-1) from step t-1 */
            float left = __shfl_up_sync(0xffffffffu, c.w, 1);
            if (lane == 0 && warp > 0)
                left = sh[(t - 1) & 1][warp - 1];

            /* all 4 mixes read OLD carries -> parallel inside the step */
            float4 nc;
            nc.x = firstcol ? (xv.x + c.x) : (xv.x + smix(c.x, left));
            nc.y = xv.y + smix(c.y, c.x);
            nc.z = xv.z + smix(c.z, c.y);
            nc.w = xv.w + smix(c.w, c.z);
            c = nc;

            __stcs(op + (size_t)t * ROW4, c);
            if (seamer) sh[t & 1][warp] = c.w;
            __syncthreads();
        }
    }
}

extern "C" void kernel_launch(void* const* d_in, const int* in_sizes, int n_in,
                              void* d_out, int out_size) {
    const float* x = (const float*)d_in[0];
    float* out = (float*)d_out;
    softscan_kernel<<<BATCH, THREADS>>>(x, out);   /* 32 CTAs, no inter-block deps */
}